// round 2
// baseline (speedup 1.0000x reference)
#include <cuda_runtime.h>

// Problem constants (fixed by the reference)
#define HH 512
#define WW 512
#define HP 64
#define WP 2048
#define BB 4
#define CC 64
#define HW (HH * WW)          // 262144 cart pixels per plane
#define PLANE (HP * WP)       // 131072 polar elements per plane

// Scratch: per-pixel inverse map. pack = y0*WP + x0 (or -1 if unmapped),
// w = (wx1, wy1) bilinear fractional weights.
__device__ int    g_pack[HW];
__device__ float2 g_w[HW];

// --- Kernel 1: reset map to sentinel -----------------------------------
__global__ void k_init_map() {
    int i = blockIdx.x * blockDim.x + threadIdx.x;
    if (i < HW) g_pack[i] = -1;
}

// --- Kernel 2: scatter grid info into per-pixel map --------------------
__global__ void k_scatter(const float* __restrict__ gx,
                          const float* __restrict__ gy,
                          const int*   __restrict__ iy,
                          const int*   __restrict__ ix,
                          int n) {
    int i = blockIdx.x * blockDim.x + threadIdx.x;
    if (i >= n) return;
    // align_corners=True: ixf = (gx+1)*(Wp-1)/2, iyf = (gy+1)*(Hp-1)/2
    float ixf = (gx[i] + 1.0f) * ((WP - 1) * 0.5f);
    float iyf = (gy[i] + 1.0f) * ((HP - 1) * 0.5f);
    float x0f = floorf(ixf);
    float y0f = floorf(iyf);
    int x0 = (int)x0f;
    int y0 = (int)y0f;
    float wx = ixf - x0f;
    float wy = iyf - y0f;
    // Analytically all corners are in range; clamp is a pure safety net.
    x0 = min(max(x0, 0), WP - 2);
    y0 = min(max(y0, 0), HP - 2);
    int p = iy[i] * WW + ix[i];
    g_pack[p] = y0 * WP + x0;
    g_w[p]    = make_float2(wx, wy);
}

// --- Kernel 3: fused sample + write, one thread per (b, y, x), loop C --
__global__ void __launch_bounds__(256)
k_main(const float* __restrict__ polar,
       const float* __restrict__ ref,
       float*       __restrict__ out) {
    int x = blockIdx.x * 256 + threadIdx.x;
    int y = blockIdx.y;
    int b = blockIdx.z;

    int p  = y * WW + x;
    int pk = g_pack[p];

    size_t base = ((size_t)b * CC) * HW + (size_t)y * WW + x;
    float* o = out + base;

    if (pk < 0) {
        // unmapped pixel: pass through ref_feat for all channels
        const float* r = ref + base;
        #pragma unroll 8
        for (int c = 0; c < CC; ++c) {
            *o = __ldg(r);
            r += HW;
            o += HW;
        }
    } else {
        float2 wv = g_w[p];
        float wx1 = wv.x, wy1 = wv.y;
        float wx0 = 1.0f - wx1, wy0 = 1.0f - wy1;
        float w00 = wx0 * wy0;
        float w01 = wx1 * wy0;
        float w10 = wx0 * wy1;
        float w11 = wx1 * wy1;

        const float* pp = polar + (size_t)b * CC * PLANE + pk;
        #pragma unroll 4
        for (int c = 0; c < CC; ++c) {
            float v00 = __ldg(pp);
            float v01 = __ldg(pp + 1);
            float v10 = __ldg(pp + WP);
            float v11 = __ldg(pp + WP + 1);
            *o = v00 * w00 + v01 * w01 + v10 * w10 + v11 * w11;
            pp += PLANE;
            o  += HW;
        }
    }
}

extern "C" void kernel_launch(void* const* d_in, const int* in_sizes, int n_in,
                              void* d_out, int out_size) {
    const float* polar = (const float*)d_in[0];   // [B,C,HP,WP]
    const float* ref   = (const float*)d_in[1];   // [B,C,H,W]
    const float* gx    = (const float*)d_in[2];   // [N]
    const float* gy    = (const float*)d_in[3];   // [N]
    const int*   iy    = (const int*)d_in[4];     // [N]
    const int*   ix    = (const int*)d_in[5];     // [N]
    float*       out   = (float*)d_out;           // [B,C,H,W]

    int n = in_sizes[2];

    k_init_map<<<(HW + 255) / 256, 256>>>();
    k_scatter<<<(n + 255) / 256, 256>>>(gx, gy, iy, ix, n);

    dim3 grid(WW / 256, HH, BB);   // (2, 512, 4) = 4096 blocks
    k_main<<<grid, 256>>>(polar, ref, out);
}